// round 16
// baseline (speedup 1.0000x reference)
#include <cuda_runtime.h>
#include <cuda_fp16.h>

// ---------------------------------------------------------------------------
// Popcnt_14731737825611 — R11: R10 + uint8 fixed-point h1/h2 storage.
// Warp = 1 output; lanes cover 8 batch columns. Layer-1 input x stays fp16
// (512B rows); h1/h2 stored as round(h*255) uint8 (256B rows -> halves the
// LTS-bound gather bytes of layers 2/3). The 1/255 scale is folded into the
// layer-2/3 pair weights; LN stats are computed from the quantized h
// (self-consistent). LN folded via C1/C2; transposed LN partials with
// coalesced finalize; final group-sum fused into pop3. 6 launches.
// ---------------------------------------------------------------------------

namespace {
constexpr int B     = 256;
constexpr int IN1   = 3200;
constexpr int O1    = 8192;
constexpr int O3    = 4096;
constexpr int P     = 128;
constexpr int NSLOT = O1 / 8;              // 1024 partial slots
constexpr int PREPB = (2 * O1 + O3) / 8;   // 2560 prep blocks
constexpr int TRB   = (IN1 / 32) * (B / 32); // 800 transpose blocks
}

// Static device scratch.
__device__ __half g_xT[IN1 * B];
__device__ uint2  g_h1u8[O1 * B / 8];      // uint8 h1, 256B rows
__device__ uint2  g_h2u8[O1 * B / 8];      // uint8 h2
__device__ uint4  g_pk1[O1 * 32];
__device__ uint4  g_pk2[O1 * 32];
__device__ uint4  g_pk3[O3 * 32];
__device__ float  g_C1b[O1], g_C2b[O1], g_C1c[O3], g_C2c[O3];
__device__ float  g_psT[B * NSLOT], g_pqT[B * NSLOT];   // [col][slot]
__device__ float  g_mu[2][B], g_rs[2][B];

__device__ __forceinline__ float sigmoidf_fast(float x) {
    return 1.0f / (1.0f + __expf(-x));
}
__device__ __forceinline__ unsigned pack_pair(int idx, float w) {
    __half h = __float2half_rn(w);
    return (unsigned)idx | ((unsigned)__half_as_ushort(h) << 16);
}
__device__ __forceinline__ float wgt(unsigned pc) {
    return __half2float(__ushort_as_half((unsigned short)(pc >> 16)));
}
__device__ __forceinline__ void fma8_h(const uint4 v, const float wv, float* acc) {
    float2 f;
    f = __half22float2(*(const __half2*)&v.x); acc[0] = fmaf(wv, f.x, acc[0]); acc[1] = fmaf(wv, f.y, acc[1]);
    f = __half22float2(*(const __half2*)&v.y); acc[2] = fmaf(wv, f.x, acc[2]); acc[3] = fmaf(wv, f.y, acc[3]);
    f = __half22float2(*(const __half2*)&v.z); acc[4] = fmaf(wv, f.x, acc[4]); acc[5] = fmaf(wv, f.y, acc[5]);
    f = __half22float2(*(const __half2*)&v.w); acc[6] = fmaf(wv, f.x, acc[6]); acc[7] = fmaf(wv, f.y, acc[7]);
}
__device__ __forceinline__ void fma8_u8(const uint2 v, const float wv, float* acc) {
    const uchar4 a = *reinterpret_cast<const uchar4*>(&v.x);
    const uchar4 b = *reinterpret_cast<const uchar4*>(&v.y);
    acc[0] = fmaf(wv, (float)a.x, acc[0]);
    acc[1] = fmaf(wv, (float)a.y, acc[1]);
    acc[2] = fmaf(wv, (float)a.z, acc[2]);
    acc[3] = fmaf(wv, (float)a.w, acc[3]);
    acc[4] = fmaf(wv, (float)b.x, acc[4]);
    acc[5] = fmaf(wv, (float)b.y, acc[5]);
    acc[6] = fmaf(wv, (float)b.z, acc[6]);
    acc[7] = fmaf(wv, (float)b.w, acc[7]);
}

// --- merged setup: prep blocks + transpose blocks --------------------------
__global__ void __launch_bounds__(256) k_setup(
    const float* __restrict__ x,
    const int* __restrict__ sel1, const float* __restrict__ w1,
    const int* __restrict__ sel2, const float* __restrict__ w2,
    const float* __restrict__ g1v, const float* __restrict__ be1,
    const int* __restrict__ sel3, const float* __restrict__ w3,
    const float* __restrict__ g2v, const float* __restrict__ be2)
{
    const int blk = blockIdx.x;
    if (blk >= PREPB) {
        // ---- transpose tile: x[B, IN1] -> g_xT[IN1, B] (fp16) ----
        __shared__ float t[32][33];
        const int tb = blk - PREPB;
        const int i0 = (tb % (IN1 / 32)) * 32;
        const int b0 = (tb / (IN1 / 32)) * 32;
        const int tx = threadIdx.x & 31, ty = threadIdx.x >> 5;  // ty 0..7
#pragma unroll
        for (int j = 0; j < 32; j += 8)
            t[ty + j][tx] = x[(b0 + ty + j) * IN1 + (i0 + tx)];
        __syncthreads();
#pragma unroll
        for (int j = 0; j < 32; j += 8)
            g_xT[(i0 + ty + j) * B + (b0 + tx)] = __float2half_rn(t[tx][ty + j]);
        return;
    }

    // ---- prep: warp = 1 output ----
    const int gw   = blk * 8 + (threadIdx.x >> 5);
    const int lane = threadIdx.x & 31;

    int layer, o;
    const int* sel; const float* w; const float* gm; const float* bt;
    uint4* pk; float* C1; float* C2;
    if (gw < O1)           { layer = 1; o = gw;          sel = sel1; w = w1; gm = nullptr; bt = nullptr; pk = g_pk1; C1 = nullptr; C2 = nullptr; }
    else if (gw < 2 * O1)  { layer = 2; o = gw - O1;     sel = sel2; w = w2; gm = g1v;    bt = be1;     pk = g_pk2; C1 = g_C1b;  C2 = g_C2b; }
    else                   { layer = 3; o = gw - 2 * O1; sel = sel3; w = w3; gm = g2v;    bt = be2;     pk = g_pk3; C1 = g_C1c;  C2 = g_C2c; }

    const int4   s4 = reinterpret_cast<const int4*>(sel + o * P)[lane];
    const float4 w4 = reinterpret_cast<const float4*>(w   + o * P)[lane];
    const int   idx[4] = { s4.x, s4.y, s4.z, s4.w };
    const float sg[4]  = { sigmoidf_fast(w4.x), sigmoidf_fast(w4.y),
                           sigmoidf_fast(w4.z), sigmoidf_fast(w4.w) };
    unsigned pc[4];
    float c1 = 0.f, c2 = 0.f;
#pragma unroll
    for (int j = 0; j < 4; ++j) {
        float sw = sg[j];
        if (layer > 1) {
            const float swg = sw * __ldg(gm + idx[j]);
            c1 += swg;                              // h-units (for mu fold)
            c2 = fmaf(sg[j], __ldg(bt + idx[j]), c2);
            sw = swg * (1.0f / 255.0f);             // fold uint8 scale
        }
        pc[j] = pack_pair(idx[j], sw);
    }
    pk[o * 32 + lane] = make_uint4(pc[0], pc[1], pc[2], pc[3]);
    if (layer > 1) {
#pragma unroll
        for (int st = 16; st > 0; st >>= 1) {
            c1 += __shfl_xor_sync(0xffffffffu, c1, st);
            c2 += __shfl_xor_sync(0xffffffffu, c2, st);
        }
        if (lane == 0) { C1[o] = c1; C2[o] = c2; }
    }
}

// --- popcnt layer: warp = 1 output, lane = 8 batch columns -----------------
// L=1: fp16 gathers (512B rows). L=2,3: uint8 gathers (256B rows).
// L=1,2: block 256 (8 warps), grid O1/8; fused LN partial per CTA.
// L=3:   block 512 (16 warps = one output group), grid O3/16; fused final.
template <int L>
__global__ void __launch_bounds__((L == 3) ? 512 : 256) k_pop(
    const float* __restrict__ bias, float* __restrict__ out)
{
    constexpr int WARPS = (L == 3) ? 16 : 8;
    __shared__ float sh[WARPS][B];

    const uint2*  inU8 = (L == 2) ? g_h1u8 : g_h2u8;   // L==1 uses g_xT
    const uint4*  pk   = (L == 1) ? g_pk1 : (L == 2) ? g_pk2 : g_pk3;
    uint2*        outU8 = (L == 1) ? g_h1u8 : g_h2u8;

    const int tid  = threadIdx.x;
    const int wid  = tid >> 5;
    const int lane = tid & 31;
    const int o    = blockIdx.x * WARPS + wid;

    const uint4* pq = pk + o * 32;
    uint4 qd = __ldg(pq);
    float acc[8];
#pragma unroll
    for (int j = 0; j < 8; ++j) acc[j] = 0.f;

#pragma unroll 4
    for (int q = 0; q < 32; ++q) {
        const uint4 qn = __ldg(pq + ((q + 1) & 31));
        const unsigned p0 = qd.x, p1 = qd.y, p2 = qd.z, p3 = qd.w;
        if (L == 1) {
            const uint4 v0 = *(reinterpret_cast<const uint4*>(g_xT + (p0 & 0xFFFFu) * B) + lane);
            const uint4 v1 = *(reinterpret_cast<const uint4*>(g_xT + (p1 & 0xFFFFu) * B) + lane);
            const uint4 v2 = *(reinterpret_cast<const uint4*>(g_xT + (p2 & 0xFFFFu) * B) + lane);
            const uint4 v3 = *(reinterpret_cast<const uint4*>(g_xT + (p3 & 0xFFFFu) * B) + lane);
            fma8_h(v0, wgt(p0), acc);
            fma8_h(v1, wgt(p1), acc);
            fma8_h(v2, wgt(p2), acc);
            fma8_h(v3, wgt(p3), acc);
        } else {
            const uint2 v0 = __ldg(inU8 + (p0 & 0xFFFFu) * 32 + lane);
            const uint2 v1 = __ldg(inU8 + (p1 & 0xFFFFu) * 32 + lane);
            const uint2 v2 = __ldg(inU8 + (p2 & 0xFFFFu) * 32 + lane);
            const uint2 v3 = __ldg(inU8 + (p3 & 0xFFFFu) * 32 + lane);
            fma8_u8(v0, wgt(p0), acc);
            fma8_u8(v1, wgt(p1), acc);
            fma8_u8(v2, wgt(p2), acc);
            fma8_u8(v3, wgt(p3), acc);
        }
        qd = qn;
    }

    // epilogue: (folded input-LN) + bias + sigmoid
    const float bo = __ldg(bias + o);
    float h[8];
    if (L > 1) {
        const float c1  = ((L == 2) ? g_C1b : g_C1c)[o];
        const float c2v = ((L == 2) ? g_C2b : g_C2c)[o];
        const float4 mA = *reinterpret_cast<const float4*>(&g_mu[L - 2][lane * 8]);
        const float4 mB = *reinterpret_cast<const float4*>(&g_mu[L - 2][lane * 8 + 4]);
        const float4 rA = *reinterpret_cast<const float4*>(&g_rs[L - 2][lane * 8]);
        const float4 rB = *reinterpret_cast<const float4*>(&g_rs[L - 2][lane * 8 + 4]);
        const float mu[8] = { mA.x, mA.y, mA.z, mA.w, mB.x, mB.y, mB.z, mB.w };
        const float rs[8] = { rA.x, rA.y, rA.z, rA.w, rB.x, rB.y, rB.z, rB.w };
#pragma unroll
        for (int j = 0; j < 8; ++j)
            h[j] = sigmoidf_fast(fmaf(rs[j], acc[j] - mu[j] * c1, c2v) - bo);
    } else {
#pragma unroll
        for (int j = 0; j < 8; ++j)
            h[j] = sigmoidf_fast(acc[j] - bo);
    }

    if (L < 3) {
        // quantize h -> uint8 (round); LN stats use the quantized values
        unsigned qb[8];
        float hq[8];
#pragma unroll
        for (int j = 0; j < 8; ++j) {
            qb[j] = __float2uint_rn(h[j] * 255.0f);
            hq[j] = (float)qb[j] * (1.0f / 255.0f);
        }
        const unsigned lo = qb[0] | (qb[1] << 8) | (qb[2] << 16) | (qb[3] << 24);
        const unsigned hi = qb[4] | (qb[5] << 8) | (qb[6] << 16) | (qb[7] << 24);
        outU8[o * 32 + lane] = make_uint2(lo, hi);
#pragma unroll
        for (int j = 0; j < 8; ++j) sh[wid][lane * 8 + j] = hq[j];
        __syncthreads();
        {
            float s = 0.f, qv = 0.f;
#pragma unroll
            for (int w = 0; w < WARPS; ++w) {
                const float v = sh[w][tid];
                s += v;
                qv = fmaf(v, v, qv);
            }
            // transposed partials: [col][slot] -> coalesced finalize reads
            g_psT[tid * NSLOT + blockIdx.x] = s;
            g_pqT[tid * NSLOT + blockIdx.x] = qv;
        }
    } else {
        // fused final: this block IS one output group of 16
#pragma unroll
        for (int j = 0; j < 8; ++j) sh[wid][lane * 8 + j] = h[j];
        __syncthreads();
        if (tid < B) {
            float s = 0.f;
#pragma unroll
            for (int w = 0; w < 16; ++w) s += sh[w][tid];
            out[tid * 256 + blockIdx.x] = s - 8.0f;
        }
    }
}

// --- LN finalize: block per column, fully coalesced ------------------------
template <int LI>
__global__ void __launch_bounds__(256) k_fin() {
    __shared__ float ss[256], sq[256];
    const int col = blockIdx.x;
    const int t   = threadIdx.x;
    const float* ps = g_psT + col * NSLOT;
    const float* pq = g_pqT + col * NSLOT;
    float s = 0.f, q = 0.f;
#pragma unroll
    for (int k = 0; k < NSLOT / 256; ++k) {
        s += ps[t + k * 256];
        q += pq[t + k * 256];
    }
    ss[t] = s; sq[t] = q;
    __syncthreads();
    for (int st = 128; st > 0; st >>= 1) {
        if (t < st) { ss[t] += ss[t + st]; sq[t] += sq[t + st]; }
        __syncthreads();
    }
    if (t == 0) {
        const float inv = 1.0f / (float)O1;
        const float m   = ss[0] * inv;
        const float var = sq[0] * inv - m * m;
        g_mu[LI][col] = m;
        g_rs[LI][col] = rsqrtf(var + 1e-12f);
    }
}

// ---------------------------------------------------------------------------
extern "C" void kernel_launch(void* const* d_in, const int* in_sizes, int n_in,
                              void* d_out, int out_size) {
    (void)in_sizes; (void)n_in; (void)out_size;
    const float* x    = (const float*)d_in[0];
    const int*   sel1 = (const int*)  d_in[1];
    const float* w1   = (const float*)d_in[2];
    const float* b1   = (const float*)d_in[3];
    const float* g1   = (const float*)d_in[4];
    const float* be1  = (const float*)d_in[5];
    const int*   sel2 = (const int*)  d_in[6];
    const float* w2   = (const float*)d_in[7];
    const float* b2   = (const float*)d_in[8];
    const float* g2   = (const float*)d_in[9];
    const float* be2  = (const float*)d_in[10];
    const int*   sel3 = (const int*)  d_in[11];
    const float* w3   = (const float*)d_in[12];
    const float* b3   = (const float*)d_in[13];
    float* out = (float*)d_out;

    k_setup<<<PREPB + TRB, 256>>>(x, sel1, w1, sel2, w2, g1, be1,
                                  sel3, w3, g2, be2);

    k_pop<1><<<O1 / 8, 256>>>(b1, nullptr);
    k_fin<0><<<B, 256>>>();
    k_pop<2><<<O1 / 8, 256>>>(b2, nullptr);
    k_fin<1><<<B, 256>>>();
    k_pop<3><<<O3 / 16, 512>>>(b3, out);
}

// round 17
// speedup vs baseline: 1.2515x; 1.2515x over previous
#include <cuda_runtime.h>
#include <cuda_fp16.h>

// ---------------------------------------------------------------------------
// Popcnt_14731737825611 — R12: uint8 activations + exact int16xuint8 DP2A
// dot products for layers 2/3; fp16 path for layer 1.
// Warp = 1 output; lanes cover 8 batch columns. h1/h2 stored round(h*255)
// uint8 (256B rows). Layer-2/3 weights quantized per-output to int16
// (scale stored per output); PRMT packs 4 p-bytes per batch column, DP2A
// accumulates in int32 exactly. LN folded via C1/C2 (h-units); transposed
// LN partials + coalesced finalize; final group-sum fused into pop3.
// ---------------------------------------------------------------------------

namespace {
constexpr int B     = 256;
constexpr int IN1   = 3200;
constexpr int O1    = 8192;
constexpr int O3    = 4096;
constexpr int P     = 128;
constexpr int NSLOT = O1 / 8;              // 1024 partial slots
constexpr int PREPB = (2 * O1 + O3) / 8;   // 2560 prep blocks
constexpr int TRB   = (IN1 / 32) * (B / 32); // 800 transpose blocks
}

// Static device scratch.
__device__ __half g_xT[IN1 * B];
__device__ uint2  g_h1u8[O1 * B / 8];      // uint8 h1, 256B rows
__device__ uint2  g_h2u8[O1 * B / 8];      // uint8 h2
__device__ uint4  g_pk1[O1 * 32];          // L1: 4 x (u16 idx | half w)
__device__ uint4  g_pk2[O1 * 32];          // L2: {idx01, idx23, w01, w23}
__device__ uint4  g_pk3[O3 * 32];          // L3: same int format
__device__ float  g_C1b[O1], g_C2b[O1], g_C1c[O3], g_C2c[O3];
__device__ float  g_S2[O1], g_S3[O3];      // per-output dequant scale (s/255)
__device__ float  g_psT[B * NSLOT], g_pqT[B * NSLOT];   // [col][slot]
__device__ float  g_mu[2][B], g_rs[2][B];

__device__ __forceinline__ float sigmoidf_fast(float x) {
    return 1.0f / (1.0f + __expf(-x));
}
__device__ __forceinline__ unsigned pack_pair(int idx, float w) {
    __half h = __float2half_rn(w);
    return (unsigned)idx | ((unsigned)__half_as_ushort(h) << 16);
}
__device__ __forceinline__ float wgt(unsigned pc) {
    return __half2float(__ushort_as_half((unsigned short)(pc >> 16)));
}
__device__ __forceinline__ void fma8_h(const uint4 v, const float wv, float* acc) {
    float2 f;
    f = __half22float2(*(const __half2*)&v.x); acc[0] = fmaf(wv, f.x, acc[0]); acc[1] = fmaf(wv, f.y, acc[1]);
    f = __half22float2(*(const __half2*)&v.y); acc[2] = fmaf(wv, f.x, acc[2]); acc[3] = fmaf(wv, f.y, acc[3]);
    f = __half22float2(*(const __half2*)&v.z); acc[4] = fmaf(wv, f.x, acc[4]); acc[5] = fmaf(wv, f.y, acc[5]);
    f = __half22float2(*(const __half2*)&v.w); acc[6] = fmaf(wv, f.x, acc[6]); acc[7] = fmaf(wv, f.y, acc[7]);
}
__device__ __forceinline__ int dp2a_lo(unsigned a, unsigned b, int c) {
    int d;
    asm("dp2a.lo.s32.u32 %0, %1, %2, %3;" : "=r"(d) : "r"(a), "r"(b), "r"(c));
    return d;
}
__device__ __forceinline__ int dp2a_hi(unsigned a, unsigned b, int c) {
    int d;
    asm("dp2a.hi.s32.u32 %0, %1, %2, %3;" : "=r"(d) : "r"(a), "r"(b), "r"(c));
    return d;
}
// accumulate 4 p-terms into 4 int accumulators from one 32-bit value word each
__device__ __forceinline__ void dp4x(unsigned w01, unsigned w23,
                                     unsigned x0, unsigned x1, unsigned x2, unsigned x3,
                                     int* accI, int base) {
#pragma unroll
    for (int k = 0; k < 4; ++k) {
        const unsigned sel1 = 0x40u + 0x11u * k;
        const unsigned t1 = __byte_perm(x0, x1, sel1);
        const unsigned t2 = __byte_perm(x2, x3, sel1);
        const unsigned vp = __byte_perm(t1, t2, 0x5410u);
        accI[base + k] = dp2a_lo(w01, vp, accI[base + k]);
        accI[base + k] = dp2a_hi(w23, vp, accI[base + k]);
    }
}

// --- merged setup: prep blocks + transpose blocks --------------------------
__global__ void __launch_bounds__(256) k_setup(
    const float* __restrict__ x,
    const int* __restrict__ sel1, const float* __restrict__ w1,
    const int* __restrict__ sel2, const float* __restrict__ w2,
    const float* __restrict__ g1v, const float* __restrict__ be1,
    const int* __restrict__ sel3, const float* __restrict__ w3,
    const float* __restrict__ g2v, const float* __restrict__ be2)
{
    const int blk = blockIdx.x;
    if (blk >= PREPB) {
        // ---- transpose tile: x[B, IN1] -> g_xT[IN1, B] (fp16) ----
        __shared__ float t[32][33];
        const int tb = blk - PREPB;
        const int i0 = (tb % (IN1 / 32)) * 32;
        const int b0 = (tb / (IN1 / 32)) * 32;
        const int tx = threadIdx.x & 31, ty = threadIdx.x >> 5;  // ty 0..7
#pragma unroll
        for (int j = 0; j < 32; j += 8)
            t[ty + j][tx] = x[(b0 + ty + j) * IN1 + (i0 + tx)];
        __syncthreads();
#pragma unroll
        for (int j = 0; j < 32; j += 8)
            g_xT[(i0 + ty + j) * B + (b0 + tx)] = __float2half_rn(t[tx][ty + j]);
        return;
    }

    // ---- prep: warp = 1 output ----
    const int gw   = blk * 8 + (threadIdx.x >> 5);
    const int lane = threadIdx.x & 31;

    int layer, o;
    const int* sel; const float* w; const float* gm; const float* bt;
    uint4* pk; float* C1; float* C2; float* Sd;
    if (gw < O1)           { layer = 1; o = gw;          sel = sel1; w = w1; gm = nullptr; bt = nullptr; pk = g_pk1; C1 = nullptr; C2 = nullptr; Sd = nullptr; }
    else if (gw < 2 * O1)  { layer = 2; o = gw - O1;     sel = sel2; w = w2; gm = g1v;    bt = be1;     pk = g_pk2; C1 = g_C1b;  C2 = g_C2b;  Sd = g_S2; }
    else                   { layer = 3; o = gw - 2 * O1; sel = sel3; w = w3; gm = g2v;    bt = be2;     pk = g_pk3; C1 = g_C1c;  C2 = g_C2c;  Sd = g_S3; }

    const int4   s4 = reinterpret_cast<const int4*>(sel + o * P)[lane];
    const float4 w4 = reinterpret_cast<const float4*>(w   + o * P)[lane];
    const int   idx[4] = { s4.x, s4.y, s4.z, s4.w };
    const float sg[4]  = { sigmoidf_fast(w4.x), sigmoidf_fast(w4.y),
                           sigmoidf_fast(w4.z), sigmoidf_fast(w4.w) };

    if (layer == 1) {
        uint4 q;
        q.x = pack_pair(idx[0], sg[0]);
        q.y = pack_pair(idx[1], sg[1]);
        q.z = pack_pair(idx[2], sg[2]);
        q.w = pack_pair(idx[3], sg[3]);
        pk[o * 32 + lane] = q;
        return;
    }

    // layers 2/3: swg = sig(w)*gamma[sel] (h-units), int16 quantization
    float swg[4];
    float c1 = 0.f, c2 = 0.f, am = 0.f;
#pragma unroll
    for (int j = 0; j < 4; ++j) {
        swg[j] = sg[j] * __ldg(gm + idx[j]);
        c1 += swg[j];
        c2 = fmaf(sg[j], __ldg(bt + idx[j]), c2);
        am = fmaxf(am, fabsf(swg[j]));
    }
#pragma unroll
    for (int st = 16; st > 0; st >>= 1) {
        c1 += __shfl_xor_sync(0xffffffffu, c1, st);
        c2 += __shfl_xor_sync(0xffffffffu, c2, st);
        am = fmaxf(am, __shfl_xor_sync(0xffffffffu, am, st));
    }
    const float s_o  = fmaxf(am, 1e-30f) * (1.0f / 32767.0f);
    const float invs = 1.0f / s_o;
    int w16[4];
#pragma unroll
    for (int j = 0; j < 4; ++j)
        w16[j] = __float2int_rn(swg[j] * invs);     // |w16| <= 32767

    uint4 q;
    q.x = ((unsigned)idx[0] & 0xFFFFu) | ((unsigned)idx[1] << 16);
    q.y = ((unsigned)idx[2] & 0xFFFFu) | ((unsigned)idx[3] << 16);
    q.z = ((unsigned)w16[0] & 0xFFFFu) | ((unsigned)w16[1] << 16);
    q.w = ((unsigned)w16[2] & 0xFFFFu) | ((unsigned)w16[3] << 16);
    pk[o * 32 + lane] = q;
    if (lane == 0) {
        C1[o] = c1;
        C2[o] = c2;
        Sd[o] = s_o * (1.0f / 255.0f);              // int-acc -> h-units
    }
}

// --- popcnt layer ----------------------------------------------------------
// L=1: fp16 gathers + FFMA (512B rows).  L=2,3: uint8 gathers + DP2A.
// L=1,2: block 256 (8 warps), grid O1/8; fused LN partial per CTA.
// L=3:   block 512 (16 warps = one output group), grid O3/16; fused final.
template <int L>
__global__ void __launch_bounds__((L == 3) ? 512 : 256) k_pop(
    const float* __restrict__ bias, float* __restrict__ out)
{
    constexpr int WARPS = (L == 3) ? 16 : 8;
    __shared__ float sh[WARPS][B];

    const uint2*  inU8 = (L == 2) ? g_h1u8 : g_h2u8;   // L==1 uses g_xT
    const uint4*  pk   = (L == 1) ? g_pk1 : (L == 2) ? g_pk2 : g_pk3;
    uint2*        outU8 = (L == 1) ? g_h1u8 : g_h2u8;

    const int tid  = threadIdx.x;
    const int wid  = tid >> 5;
    const int lane = tid & 31;
    const int o    = blockIdx.x * WARPS + wid;

    const uint4* pq = pk + o * 32;
    uint4 qd = __ldg(pq);

    float acc[(L == 1) ? 8 : 1];
    int   accI[(L == 1) ? 1 : 8];
#pragma unroll
    for (int j = 0; j < ((L == 1) ? 8 : 1); ++j) acc[j] = 0.f;
#pragma unroll
    for (int j = 0; j < ((L == 1) ? 1 : 8); ++j) accI[j] = 0;

#pragma unroll 4
    for (int q = 0; q < 32; ++q) {
        const uint4 qn = __ldg(pq + ((q + 1) & 31));
        if (L == 1) {
            const unsigned p0 = qd.x, p1 = qd.y, p2 = qd.z, p3 = qd.w;
            const uint4 v0 = *(reinterpret_cast<const uint4*>(g_xT + (p0 & 0xFFFFu) * B) + lane);
            const uint4 v1 = *(reinterpret_cast<const uint4*>(g_xT + (p1 & 0xFFFFu) * B) + lane);
            const uint4 v2 = *(reinterpret_cast<const uint4*>(g_xT + (p2 & 0xFFFFu) * B) + lane);
            const uint4 v3 = *(reinterpret_cast<const uint4*>(g_xT + (p3 & 0xFFFFu) * B) + lane);
            fma8_h(v0, wgt(p0), acc);
            fma8_h(v1, wgt(p1), acc);
            fma8_h(v2, wgt(p2), acc);
            fma8_h(v3, wgt(p3), acc);
        } else {
            const int i0 = (int)(qd.x & 0xFFFFu), i1 = (int)(qd.x >> 16);
            const int i2 = (int)(qd.y & 0xFFFFu), i3 = (int)(qd.y >> 16);
            const uint2 v0 = __ldg(inU8 + i0 * 32 + lane);
            const uint2 v1 = __ldg(inU8 + i1 * 32 + lane);
            const uint2 v2 = __ldg(inU8 + i2 * 32 + lane);
            const uint2 v3 = __ldg(inU8 + i3 * 32 + lane);
            dp4x(qd.z, qd.w, v0.x, v1.x, v2.x, v3.x, accI, 0);  // cols 0..3
            dp4x(qd.z, qd.w, v0.y, v1.y, v2.y, v3.y, accI, 4);  // cols 4..7
        }
        qd = qn;
    }

    // epilogue: (folded input-LN) + bias + sigmoid
    const float bo = __ldg(bias + o);
    float h[8];
    if (L > 1) {
        const float sc  = ((L == 2) ? g_S2 : g_S3)[o];
        const float c1  = ((L == 2) ? g_C1b : g_C1c)[o];
        const float c2v = ((L == 2) ? g_C2b : g_C2c)[o];
        const float4 mA = *reinterpret_cast<const float4*>(&g_mu[L - 2][lane * 8]);
        const float4 mB = *reinterpret_cast<const float4*>(&g_mu[L - 2][lane * 8 + 4]);
        const float4 rA = *reinterpret_cast<const float4*>(&g_rs[L - 2][lane * 8]);
        const float4 rB = *reinterpret_cast<const float4*>(&g_rs[L - 2][lane * 8 + 4]);
        const float mu[8] = { mA.x, mA.y, mA.z, mA.w, mB.x, mB.y, mB.z, mB.w };
        const float rs[8] = { rA.x, rA.y, rA.z, rA.w, rB.x, rB.y, rB.z, rB.w };
#pragma unroll
        for (int j = 0; j < 8; ++j) {
            const float A = (float)accI[j] * sc;     // Σ swg*h  (h-units)
            h[j] = sigmoidf_fast(fmaf(rs[j], A - mu[j] * c1, c2v) - bo);
        }
    } else {
#pragma unroll
        for (int j = 0; j < 8; ++j)
            h[j] = sigmoidf_fast(acc[j] - bo);
    }

    if (L < 3) {
        // quantize h -> uint8 (round); LN stats use the quantized values
        unsigned qb[8];
        float hq[8];
#pragma unroll
        for (int j = 0; j < 8; ++j) {
            qb[j] = __float2uint_rn(h[j] * 255.0f);
            hq[j] = (float)qb[j] * (1.0f / 255.0f);
        }
        const unsigned lo = qb[0] | (qb[1] << 8) | (qb[2] << 16) | (qb[3] << 24);
        const unsigned hi = qb[4] | (qb[5] << 8) | (qb[6] << 16) | (qb[7] << 24);
        outU8[o * 32 + lane] = make_uint2(lo, hi);
#pragma unroll
        for (int j = 0; j < 8; ++j) sh[wid][lane * 8 + j] = hq[j];
        __syncthreads();
        {
            float s = 0.f, qv = 0.f;
#pragma unroll
            for (int w = 0; w < WARPS; ++w) {
                const float v = sh[w][tid];
                s += v;
                qv = fmaf(v, v, qv);
            }
            g_psT[tid * NSLOT + blockIdx.x] = s;
            g_pqT[tid * NSLOT + blockIdx.x] = qv;
        }
    } else {
        // fused final: this block IS one output group of 16
#pragma unroll
        for (int j = 0; j < 8; ++j) sh[wid][lane * 8 + j] = h[j];
        __syncthreads();
        if (tid < B) {
            float s = 0.f;
#pragma unroll
            for (int w = 0; w < 16; ++w) s += sh[w][tid];
            out[tid * 256 + blockIdx.x] = s - 8.0f;
        }
    }
}

// --- LN finalize: block per column, fully coalesced ------------------------
template <int LI>
__global__ void __launch_bounds__(256) k_fin() {
    __shared__ float ss[256], sq[256];
    const int col = blockIdx.x;
    const int t   = threadIdx.x;
    const float* ps = g_psT + col * NSLOT;
    const float* pq = g_pqT + col * NSLOT;
    float s = 0.f, q = 0.f;
#pragma unroll
    for (int k = 0; k < NSLOT / 256; ++k) {
        s += ps[t + k * 256];
        q += pq[t + k * 256];
    }
    ss[t] = s; sq[t] = q;
    __syncthreads();
    for (int st = 128; st > 0; st >>= 1) {
        if (t < st) { ss[t] += ss[t + st]; sq[t] += sq[t + st]; }
        __syncthreads();
    }
    if (t == 0) {
        const float inv = 1.0f / (float)O1;
        const float m   = ss[0] * inv;
        const float var = sq[0] * inv - m * m;
        g_mu[LI][col] = m;
        g_rs[LI][col] = rsqrtf(var + 1e-12f);
    }
}

// ---------------------------------------------------------------------------
extern "C" void kernel_launch(void* const* d_in, const int* in_sizes, int n_in,
                              void* d_out, int out_size) {
    (void)in_sizes; (void)n_in; (void)out_size;
    const float* x    = (const float*)d_in[0];
    const int*   sel1 = (const int*)  d_in[1];
    const float* w1   = (const float*)d_in[2];
    const float* b1   = (const float*)d_in[3];
    const float* g1   = (const float*)d_in[4];
    const float* be1  = (const float*)d_in[5];
    const int*   sel2 = (const int*)  d_in[6];
    const float* w2   = (const float*)d_in[7];
    const float* b2   = (const float*)d_in[8];
    const float* g2   = (const float*)d_in[9];
    const float* be2  = (const float*)d_in[10];
    const int*   sel3 = (const int*)  d_in[11];
    const float* w3   = (const float*)d_in[12];
    const float* b3   = (const float*)d_in[13];
    float* out = (float*)d_out;

    k_setup<<<PREPB + TRB, 256>>>(x, sel1, w1, sel2, w2, g1, be1,
                                  sel3, w3, g2, be2);

    k_pop<1><<<O1 / 8, 256>>>(b1, nullptr);
    k_fin<0><<<B, 256>>>();
    k_pop<2><<<O1 / 8, 256>>>(b2, nullptr);
    k_fin<1><<<B, 256>>>();
    k_pop<3><<<O3 / 16, 512>>>(b3, out);
}